// round 14
// baseline (speedup 1.0000x reference)
#include <cuda_runtime.h>
#include <cuda_fp16.h>

// ============================================================================
// Intergrator_5952824672851  (CFD cell integrator, F=6M faces, C=4M cells)
//
// per cell c, faces f0,f1,f2 = cell_face[:,c], normals n_i = unv[c,i,:]:
//   de_i = (uv_i . n_i) * area_i          (w = a*uv; de = w.n)
//   loss[c] = sum_i de_i
//   A = sum_i w_i*(de_i*inva_i) ; P = sum_i (p_i*a_i)*n_i ; D = sum_i fD_i
//   out[c] = rhs_coef[c] * (-A - P/rho[c]) + D
//
// R13 -> R14: split the cell pass into two kernels so each random table fits
// comfortably in L2 (R10/R13: 96MB table ~= L2 -> ~400MB DRAM round-trip;
// R11: small tables but 6 LDGs/cell in one kernel -> L1 wavefront ceiling):
//   T1 = 8B/face {h2(wx,wy), h2(q,inva)}  (48 MB)  -> "main" kernel, 3 LDGs
//   T2 = 4B/face {h2(fDx,fDy)}            (24 MB)  -> "d_term" kernel, 3 LDGs
//   d_term writes out2 = D; main RMWs out2 += rc*(-A - P/rho), writes loss.
// Costs +112MB streaming (cf re-read + RMW) to eliminate ~300MB of gather
// DRAM. fp16 set identical to R11 (passed, rel_err 3.5e-4).
// ============================================================================

#define MAX_F 6000000

__device__ uint2        g_t1[MAX_F];   // 48 MB: {wx|wy, q|inva}
__device__ unsigned int g_t2[MAX_F];   // 24 MB: {fDx|fDy}
__device__ int          g_idx_kind;    // 0 = int64, 1 = int32, 2 = float32

__device__ __forceinline__ unsigned pack_h2(float lo, float hi) {
    __half2 h = __halves2half2(__float2half_rn(lo), __float2half_rn(hi));
    return (unsigned)__half_as_ushort(__low2half(h)) |
           ((unsigned)__half_as_ushort(__high2half(h)) << 16);
}
__device__ __forceinline__ float unpack_lo(unsigned v) {
    return __half2float(__ushort_as_half((unsigned short)(v & 0xFFFFu)));
}
__device__ __forceinline__ float unpack_hi(unsigned v) {
    return __half2float(__ushort_as_half((unsigned short)(v >> 16)));
}

__global__ void __launch_bounds__(256)
pack_faces_kernel(const float2* __restrict__ uv_face,
                  const float*  __restrict__ p_face,
                  const float2* __restrict__ flux_D,
                  const float*  __restrict__ face_area,
                  const unsigned int* __restrict__ idx_words,
                  long long nwords,
                  int F) {
    if (blockIdx.x == 0) {   // dtype detection, single uniform barrier
        __shared__ unsigned s_oz[4], s_sm[4];
        int t = threadIdx.x;
        if (t < 128) {
            long long stride = nwords / 128;
            if (stride < 2) stride = 2;
            long long pos = stride * (long long)t;
            bool odd_zero = true, small = true;
            if (pos + 1 < nwords) {
                unsigned int lo = idx_words[pos & ~1LL];
                unsigned int hi = idx_words[pos | 1LL];
                odd_zero = (hi == 0u);
                small    = (lo < (1u << 24)) && (hi < (1u << 24) || hi == 0u);
            }
            unsigned all_oz = __ballot_sync(0xFFFFFFFFu, odd_zero);
            unsigned all_sm = __ballot_sync(0xFFFFFFFFu, small);
            if ((t & 31) == 0) { s_oz[t >> 5] = all_oz; s_sm[t >> 5] = all_sm; }
        }
        __syncthreads();
        if (t == 0) {
            bool oz = (s_oz[0] & s_oz[1] & s_oz[2] & s_oz[3]) == 0xFFFFFFFFu;
            bool sm = (s_sm[0] & s_sm[1] & s_sm[2] & s_sm[3]) == 0xFFFFFFFFu;
            g_idx_kind = oz ? 0 : (sm ? 1 : 2);
        }
    }

    int f = blockIdx.x * blockDim.x + threadIdx.x;
    if (f >= F) return;
    float2 uv = __ldcs(&uv_face[f]);
    float2 fd = __ldcs(&flux_D[f]);
    float  p  = __ldcs(&p_face[f]);
    float  a  = __ldcs(&face_area[f]);

    float wx   = a * uv.x;
    float wy   = a * uv.y;
    float q    = p * a;
    float inva = fminf(1.0f / fmaxf(a, 1e-30f), 60000.0f);  // f16-safe clamp

    g_t1[f] = make_uint2(pack_h2(wx, wy), pack_h2(q, inva));  // keep in L2
    g_t2[f] = pack_h2(fd.x, fd.y);
}

__device__ __forceinline__ long long clampF(long long v, long long F) {
    if (v < 0) v = 0;
    if (v >= F) v = F - 1;
    return v;
}
__device__ __forceinline__ long long load_idx_cs(const void* p, int kind, long long i) {
    if (kind == 0) return __ldcs(&((const long long*)p)[i]);
    if (kind == 1) return (long long)__ldcs(&((const int*)p)[i]);
    return (long long)__ldcs(&((const float*)p)[i]);
}

// ---- pass 1: diffusion term only (T2 gathers, 24MB table) ----
__global__ void __launch_bounds__(256)
d_term_kernel(const void* __restrict__ cell_face,   // [3, C]
              float*      __restrict__ out,         // [3C]
              int C, int F) {
    int c = blockIdx.x * blockDim.x + threadIdx.x;
    if (c >= C) return;
    int kind = g_idx_kind;

    long long f0 = clampF(load_idx_cs(cell_face, kind, c), F);
    long long f1 = clampF(load_idx_cs(cell_face, kind, (long long)C + c), F);
    long long f2 = clampF(load_idx_cs(cell_face, kind, 2LL * C + c), F);

    unsigned d0 = __ldcg(&g_t2[f0]);
    unsigned d1 = __ldcg(&g_t2[f1]);
    unsigned d2 = __ldcg(&g_t2[f2]);

    float Dx = unpack_lo(d0) + unpack_lo(d1) + unpack_lo(d2);
    float Dy = unpack_hi(d0) + unpack_hi(d1) + unpack_hi(d2);

    float2* o2 = reinterpret_cast<float2*>(out + C);
    o2[c] = make_float2(Dx, Dy);     // default policy: likely stays in L2 for pass 2
}

// ---- pass 2: loss + convection + pressure, RMW the D partial ----
__global__ void __launch_bounds__(256)
cell_main_kernel(const void*   __restrict__ cell_face, // [3, C]
                 const float2* __restrict__ unv,       // [C,3,2]
                 const float*  __restrict__ rho,       // [C]
                 const float*  __restrict__ rhs_coef,  // [C]
                 float*        __restrict__ out,       // [3C]
                 int C, int F) {
    int c = blockIdx.x * blockDim.x + threadIdx.x;
    if (c >= C) return;
    int kind = g_idx_kind;

    long long f0 = clampF(load_idx_cs(cell_face, kind, c), F);
    long long f1 = clampF(load_idx_cs(cell_face, kind, (long long)C + c), F);
    long long f2 = clampF(load_idx_cs(cell_face, kind, 2LL * C + c), F);

    uint2 t0 = __ldcg(&g_t1[f0]);
    uint2 t1 = __ldcg(&g_t1[f1]);
    uint2 t2 = __ldcg(&g_t1[f2]);

    float2 n0 = __ldcs(&unv[3 * c + 0]);
    float2 n1 = __ldcs(&unv[3 * c + 1]);
    float2 n2 = __ldcs(&unv[3 * c + 2]);

    float wx0 = unpack_lo(t0.x), wy0 = unpack_hi(t0.x);
    float wx1 = unpack_lo(t1.x), wy1 = unpack_hi(t1.x);
    float wx2 = unpack_lo(t2.x), wy2 = unpack_hi(t2.x);
    float q0 = unpack_lo(t0.y), ia0 = unpack_hi(t0.y);
    float q1 = unpack_lo(t1.y), ia1 = unpack_hi(t1.y);
    float q2 = unpack_lo(t2.y), ia2 = unpack_hi(t2.y);

    float de0 = wx0 * n0.x + wy0 * n0.y;
    float de1 = wx1 * n1.x + wy1 * n1.y;
    float de2 = wx2 * n2.x + wy2 * n2.y;

    float loss = de0 + de1 + de2;

    float s0 = de0 * ia0;
    float s1 = de1 * ia1;
    float s2 = de2 * ia2;

    float Ax = wx0 * s0 + wx1 * s1 + wx2 * s2;   // w*inva = uv
    float Ay = wy0 * s0 + wy1 * s1 + wy2 * s2;

    float Px = q0 * n0.x + q1 * n1.x + q2 * n2.x;
    float Py = q0 * n0.y + q1 * n1.y + q2 * n2.y;

    float inv_rho = 1.0f / __ldcs(&rho[c]);
    float rc = __ldcs(&rhs_coef[c]);

    float2* o2 = reinterpret_cast<float2*>(out + C);
    float2 D = o2[c];                               // written by d_term (L2 hit)

    float ox = rc * (-Ax - inv_rho * Px) + D.x;
    float oy = rc * (-Ay - inv_rho * Py) + D.y;

    __stcs(&out[c], loss);                          // loss_continuity [C,1]
    __stcs(&o2[c], make_float2(ox, oy));            // out [C,2]
}

extern "C" void kernel_launch(void* const* d_in, const int* in_sizes, int n_in,
                              void* d_out, int out_size) {
    // 0 uv_face [F,2] f32 | 1 p_face [F,1] f32 | 2 flux_D [F,2] f32
    // 3 unv [C,3,2] f32   | 4 rho [C,1] f32    | 5 rhs_coef [C,1] f32
    // 6 face_area [F,1] f32 | 7 cell_face [3,C] (int64 or downcast)
    const float2* uv_face   = (const float2*)d_in[0];
    const float*  p_face    = (const float*) d_in[1];
    const float2* flux_D    = (const float2*)d_in[2];
    const float2* unv       = (const float2*)d_in[3];
    const float*  rho       = (const float*) d_in[4];
    const float*  rhs_coef  = (const float*) d_in[5];
    const float*  face_area = (const float*) d_in[6];
    const void*   cell_face = d_in[7];

    int F = in_sizes[1];   // p_face element count
    int C = in_sizes[4];   // rho element count
    float* out = (float*)d_out;

    long long nwords = 3LL * C;

    const int TPB = 256;
    pack_faces_kernel<<<(F + TPB - 1) / TPB, TPB>>>(uv_face, p_face, flux_D, face_area,
                                                    (const unsigned int*)cell_face,
                                                    nwords, F);
    d_term_kernel<<<(C + TPB - 1) / TPB, TPB>>>(cell_face, out, C, F);
    cell_main_kernel<<<(C + TPB - 1) / TPB, TPB>>>(cell_face, unv, rho, rhs_coef,
                                                   out, C, F);
}

// round 15
// speedup vs baseline: 1.0100x; 1.0100x over previous
#include <cuda_runtime.h>
#include <cuda_fp16.h>

// ============================================================================
// Intergrator_5952824672851  (CFD cell integrator, F=6M faces, C=4M cells)
//
// per cell c, faces f0,f1,f2 = cell_face[:,c], normals n_i = unv[c,i,:]:
//   de_i = (uv_i . n_i) * area_i          (w = a*uv; de = w.n)
//   loss[c] = sum_i de_i
//   A = sum_i w_i*(de_i*inva_i) ; P = sum_i (p_i*a_i)*n_i ; D = sum_i fD_i
//   out[c] = rhs_coef[c] * (-A - P/rho[c]) + D
//
// R14 -> R15: split done right.
//   - fD is NEVER packed: d_term gathers straight from the flux_D input
//     (48 MB f32, L2-friendly) and writes o2 = D.   (R14 wasted a 24MB pack)
//   - T1 = 8B/face {h2(wx,wy), h2(q,inva)} = 48 MB -> good L2 residency in
//     main (3 LDGs/cell, no R11 L1-wavefront problem).
//   - order pack -> d_term -> main so o2 (32MB) is L2-hot for main's RMW.
// Byte budget ~626MB vs R10's ~880MB.
// ============================================================================

#define MAX_F 6000000

__device__ uint2 g_t1[MAX_F];   // 48 MB: {wx|wy, q|inva} (f16x2 pairs)
__device__ int   g_idx_kind;    // 0 = int64, 1 = int32, 2 = float32

__device__ __forceinline__ unsigned pack_h2(float lo, float hi) {
    __half2 h = __halves2half2(__float2half_rn(lo), __float2half_rn(hi));
    return (unsigned)__half_as_ushort(__low2half(h)) |
           ((unsigned)__half_as_ushort(__high2half(h)) << 16);
}
__device__ __forceinline__ float unpack_lo(unsigned v) {
    return __half2float(__ushort_as_half((unsigned short)(v & 0xFFFFu)));
}
__device__ __forceinline__ float unpack_hi(unsigned v) {
    return __half2float(__ushort_as_half((unsigned short)(v >> 16)));
}

__global__ void __launch_bounds__(256)
pack_faces_kernel(const float2* __restrict__ uv_face,
                  const float*  __restrict__ p_face,
                  const float*  __restrict__ face_area,
                  const unsigned int* __restrict__ idx_words,
                  long long nwords,
                  int F) {
    if (blockIdx.x == 0) {   // dtype detection, single uniform barrier
        __shared__ unsigned s_oz[4], s_sm[4];
        int t = threadIdx.x;
        if (t < 128) {
            long long stride = nwords / 128;
            if (stride < 2) stride = 2;
            long long pos = stride * (long long)t;
            bool odd_zero = true, small = true;
            if (pos + 1 < nwords) {
                unsigned int lo = idx_words[pos & ~1LL];
                unsigned int hi = idx_words[pos | 1LL];
                odd_zero = (hi == 0u);
                small    = (lo < (1u << 24)) && (hi < (1u << 24) || hi == 0u);
            }
            unsigned all_oz = __ballot_sync(0xFFFFFFFFu, odd_zero);
            unsigned all_sm = __ballot_sync(0xFFFFFFFFu, small);
            if ((t & 31) == 0) { s_oz[t >> 5] = all_oz; s_sm[t >> 5] = all_sm; }
        }
        __syncthreads();
        if (t == 0) {
            bool oz = (s_oz[0] & s_oz[1] & s_oz[2] & s_oz[3]) == 0xFFFFFFFFu;
            bool sm = (s_sm[0] & s_sm[1] & s_sm[2] & s_sm[3]) == 0xFFFFFFFFu;
            g_idx_kind = oz ? 0 : (sm ? 1 : 2);
        }
    }

    int f = blockIdx.x * blockDim.x + threadIdx.x;
    if (f >= F) return;
    float2 uv = __ldcs(&uv_face[f]);
    float  p  = __ldcs(&p_face[f]);
    float  a  = __ldcs(&face_area[f]);

    float wx   = a * uv.x;
    float wy   = a * uv.y;
    float q    = p * a;
    float inva = fminf(1.0f / fmaxf(a, 1e-30f), 60000.0f);  // f16-safe clamp

    g_t1[f] = make_uint2(pack_h2(wx, wy), pack_h2(q, inva));  // keep in L2
}

__device__ __forceinline__ long long clampF(long long v, long long F) {
    if (v < 0) v = 0;
    if (v >= F) v = F - 1;
    return v;
}
__device__ __forceinline__ long long load_idx_cs(const void* p, int kind, long long i) {
    if (kind == 0) return __ldcs(&((const long long*)p)[i]);
    if (kind == 1) return (long long)__ldcs(&((const int*)p)[i]);
    return (long long)__ldcs(&((const float*)p)[i]);
}

// ---- pass A: diffusion term, gathered straight from the flux_D input ----
__global__ void __launch_bounds__(256)
d_term_kernel(const void*   __restrict__ cell_face,  // [3, C]
              const float2* __restrict__ flux_D,     // [F] f32x2 input (48 MB)
              float*        __restrict__ out,        // [3C]
              int C, int F) {
    int c = blockIdx.x * blockDim.x + threadIdx.x;
    if (c >= C) return;
    int kind = g_idx_kind;

    long long f0 = clampF(load_idx_cs(cell_face, kind, c), F);
    long long f1 = clampF(load_idx_cs(cell_face, kind, (long long)C + c), F);
    long long f2 = clampF(load_idx_cs(cell_face, kind, 2LL * C + c), F);

    float2 d0 = __ldcg(&flux_D[f0]);
    float2 d1 = __ldcg(&flux_D[f1]);
    float2 d2 = __ldcg(&flux_D[f2]);

    float2* o2 = reinterpret_cast<float2*>(out + C);
    o2[c] = make_float2(d0.x + d1.x + d2.x, d0.y + d1.y + d2.y);  // stays L2-hot
}

// ---- pass B: loss + convection + pressure; RMW the D partial ----
__global__ void __launch_bounds__(256)
cell_main_kernel(const void*   __restrict__ cell_face, // [3, C]
                 const float2* __restrict__ unv,       // [C,3,2]
                 const float*  __restrict__ rho,       // [C]
                 const float*  __restrict__ rhs_coef,  // [C]
                 float*        __restrict__ out,       // [3C]
                 int C, int F) {
    int c = blockIdx.x * blockDim.x + threadIdx.x;
    if (c >= C) return;
    int kind = g_idx_kind;

    long long f0 = clampF(load_idx_cs(cell_face, kind, c), F);
    long long f1 = clampF(load_idx_cs(cell_face, kind, (long long)C + c), F);
    long long f2 = clampF(load_idx_cs(cell_face, kind, 2LL * C + c), F);

    uint2 t0 = __ldcg(&g_t1[f0]);
    uint2 t1 = __ldcg(&g_t1[f1]);
    uint2 t2 = __ldcg(&g_t1[f2]);

    float2 n0 = __ldcs(&unv[3 * c + 0]);
    float2 n1 = __ldcs(&unv[3 * c + 1]);
    float2 n2 = __ldcs(&unv[3 * c + 2]);

    float wx0 = unpack_lo(t0.x), wy0 = unpack_hi(t0.x);
    float wx1 = unpack_lo(t1.x), wy1 = unpack_hi(t1.x);
    float wx2 = unpack_lo(t2.x), wy2 = unpack_hi(t2.x);
    float q0 = unpack_lo(t0.y), ia0 = unpack_hi(t0.y);
    float q1 = unpack_lo(t1.y), ia1 = unpack_hi(t1.y);
    float q2 = unpack_lo(t2.y), ia2 = unpack_hi(t2.y);

    float de0 = wx0 * n0.x + wy0 * n0.y;
    float de1 = wx1 * n1.x + wy1 * n1.y;
    float de2 = wx2 * n2.x + wy2 * n2.y;

    float loss = de0 + de1 + de2;

    float s0 = de0 * ia0;
    float s1 = de1 * ia1;
    float s2 = de2 * ia2;

    float Ax = wx0 * s0 + wx1 * s1 + wx2 * s2;   // w*inva = uv
    float Ay = wy0 * s0 + wy1 * s1 + wy2 * s2;

    float Px = q0 * n0.x + q1 * n1.x + q2 * n2.x;
    float Py = q0 * n0.y + q1 * n1.y + q2 * n2.y;

    float inv_rho = 1.0f / __ldcs(&rho[c]);
    float rc = __ldcs(&rhs_coef[c]);

    float2* o2 = reinterpret_cast<float2*>(out + C);
    float2 D = o2[c];                               // written by d_term (L2 hit)

    float ox = rc * (-Ax - inv_rho * Px) + D.x;
    float oy = rc * (-Ay - inv_rho * Py) + D.y;

    __stcs(&out[c], loss);                          // loss_continuity [C,1]
    __stcs(&o2[c], make_float2(ox, oy));            // out [C,2]
}

extern "C" void kernel_launch(void* const* d_in, const int* in_sizes, int n_in,
                              void* d_out, int out_size) {
    // 0 uv_face [F,2] f32 | 1 p_face [F,1] f32 | 2 flux_D [F,2] f32
    // 3 unv [C,3,2] f32   | 4 rho [C,1] f32    | 5 rhs_coef [C,1] f32
    // 6 face_area [F,1] f32 | 7 cell_face [3,C] (int64 or downcast)
    const float2* uv_face   = (const float2*)d_in[0];
    const float*  p_face    = (const float*) d_in[1];
    const float2* flux_D    = (const float2*)d_in[2];
    const float2* unv       = (const float2*)d_in[3];
    const float*  rho       = (const float*) d_in[4];
    const float*  rhs_coef  = (const float*) d_in[5];
    const float*  face_area = (const float*) d_in[6];
    const void*   cell_face = d_in[7];

    int F = in_sizes[1];   // p_face element count
    int C = in_sizes[4];   // rho element count
    float* out = (float*)d_out;

    long long nwords = 3LL * C;

    const int TPB = 256;
    pack_faces_kernel<<<(F + TPB - 1) / TPB, TPB>>>(uv_face, p_face, face_area,
                                                    (const unsigned int*)cell_face,
                                                    nwords, F);
    d_term_kernel<<<(C + TPB - 1) / TPB, TPB>>>(cell_face, flux_D, out, C, F);
    cell_main_kernel<<<(C + TPB - 1) / TPB, TPB>>>(cell_face, unv, rho, rhs_coef,
                                                   out, C, F);
}

// round 16
// speedup vs baseline: 1.2006x; 1.1887x over previous
#include <cuda_runtime.h>
#include <cuda_fp16.h>

// ============================================================================
// Intergrator_5952824672851  (CFD cell integrator, F=6M faces, C=4M cells)
//
// per cell c, faces f0,f1,f2 = cell_face[:,c], normals n_i = unv[c,i,:]:
//   de_i = (uv_i . n_i) * area_i          (w = a*uv; de = w.n, fp32-exact)
//   loss[c] = sum_i de_i
//   A = sum_i w_i*(de_i*inva_i) ; P = sum_i (p_i*a_i)*n_i ; D = sum_i fD_i
//   out[c] = rhs_coef[c] * (-A - P/rho[c]) + D
//
// R15 -> R16: back to the proven single-kernel 16B-record design (R13),
// with ONE change: the pack table is stored WRITE-THROUGH (__stwt) so its
// L2 lines are CLEAN. Measured R10/R13: ~400MB table DRAM round-trip =
// dirty writebacks + refetch thrash; clean lines evict for free, removing
// the writeback component (~96MB) and its latency pressure.
// Record: { wx=a*u f32, wy=a*v f32, h2(q=p*a, inva=1/a), h2(fDx,fDy) } =16B.
// ============================================================================

#define MAX_F 6000000

__device__ float4 g_rec[MAX_F];   // 96 MB table, one 32B-sector touch per gather
__device__ int    g_idx_kind;     // 0 = int64, 1 = int32, 2 = float32

__device__ __forceinline__ unsigned pack_h2(float lo, float hi) {
    __half2 h = __halves2half2(__float2half_rn(lo), __float2half_rn(hi));
    return (unsigned)__half_as_ushort(__low2half(h)) |
           ((unsigned)__half_as_ushort(__high2half(h)) << 16);
}
__device__ __forceinline__ float unpack_lo(unsigned v) {
    return __half2float(__ushort_as_half((unsigned short)(v & 0xFFFFu)));
}
__device__ __forceinline__ float unpack_hi(unsigned v) {
    return __half2float(__ushort_as_half((unsigned short)(v >> 16)));
}

__global__ void __launch_bounds__(256)
pack_faces_kernel(const float2* __restrict__ uv_face,
                  const float*  __restrict__ p_face,
                  const float2* __restrict__ flux_D,
                  const float*  __restrict__ face_area,
                  const unsigned int* __restrict__ idx_words,
                  long long nwords,
                  int F) {
    if (blockIdx.x == 0) {   // dtype detection, single uniform barrier
        __shared__ unsigned s_oz[4], s_sm[4];
        int t = threadIdx.x;
        if (t < 128) {
            long long stride = nwords / 128;
            if (stride < 2) stride = 2;
            long long pos = stride * (long long)t;
            bool odd_zero = true, small = true;
            if (pos + 1 < nwords) {
                unsigned int lo = idx_words[pos & ~1LL];
                unsigned int hi = idx_words[pos | 1LL];
                odd_zero = (hi == 0u);
                small    = (lo < (1u << 24)) && (hi < (1u << 24) || hi == 0u);
            }
            unsigned all_oz = __ballot_sync(0xFFFFFFFFu, odd_zero);
            unsigned all_sm = __ballot_sync(0xFFFFFFFFu, small);
            if ((t & 31) == 0) { s_oz[t >> 5] = all_oz; s_sm[t >> 5] = all_sm; }
        }
        __syncthreads();
        if (t == 0) {
            bool oz = (s_oz[0] & s_oz[1] & s_oz[2] & s_oz[3]) == 0xFFFFFFFFu;
            bool sm = (s_sm[0] & s_sm[1] & s_sm[2] & s_sm[3]) == 0xFFFFFFFFu;
            g_idx_kind = oz ? 0 : (sm ? 1 : 2);
        }
    }

    int f = blockIdx.x * blockDim.x + threadIdx.x;
    if (f >= F) return;
    float2 uv = __ldcs(&uv_face[f]);
    float2 fd = __ldcs(&flux_D[f]);
    float  p  = __ldcs(&p_face[f]);
    float  a  = __ldcs(&face_area[f]);

    float4 rec;
    rec.x = a * uv.x;
    rec.y = a * uv.y;
    rec.z = __uint_as_float(pack_h2(p * a, fminf(1.0f / fmaxf(a, 1e-30f), 60000.0f)));
    rec.w = __uint_as_float(pack_h2(fd.x, fd.y));

    __stwt(&g_rec[f], rec);   // WRITE-THROUGH: DRAM updated now, L2 line CLEAN
}

__device__ __forceinline__ long long clampF(long long v, long long F) {
    if (v < 0) v = 0;
    if (v >= F) v = F - 1;
    return v;
}
__device__ __forceinline__ long long load_idx_cs(const void* p, int kind, long long i) {
    if (kind == 0) return __ldcs(&((const long long*)p)[i]);
    if (kind == 1) return (long long)__ldcs(&((const int*)p)[i]);
    return (long long)__ldcs(&((const float*)p)[i]);
}

__global__ void __launch_bounds__(256)
cell_integrate_kernel(const void*   __restrict__ cell_face, // [3, C]
                      const float2* __restrict__ unv,       // [C,3,2]
                      const float*  __restrict__ rho,       // [C]
                      const float*  __restrict__ rhs_coef,  // [C]
                      float*        __restrict__ out,       // [3C]
                      int C, int F) {
    int c = blockIdx.x * blockDim.x + threadIdx.x;
    if (c >= C) return;

    int kind = g_idx_kind;

    long long f0 = clampF(load_idx_cs(cell_face, kind, c), F);
    long long f1 = clampF(load_idx_cs(cell_face, kind, (long long)C + c), F);
    long long f2 = clampF(load_idx_cs(cell_face, kind, 2LL * C + c), F);

    // 3 random gathers, one 32B sector each (table lines clean in L2)
    float4 r0 = __ldcg(&g_rec[f0]);
    float4 r1 = __ldcg(&g_rec[f1]);
    float4 r2 = __ldcg(&g_rec[f2]);

    float2 n0 = __ldcs(&unv[3 * c + 0]);
    float2 n1 = __ldcs(&unv[3 * c + 1]);
    float2 n2 = __ldcs(&unv[3 * c + 2]);

    unsigned z0 = __float_as_uint(r0.z), w0 = __float_as_uint(r0.w);
    unsigned z1 = __float_as_uint(r1.z), w1 = __float_as_uint(r1.w);
    unsigned z2 = __float_as_uint(r2.z), w2 = __float_as_uint(r2.w);

    float de0 = r0.x * n0.x + r0.y * n0.y;
    float de1 = r1.x * n1.x + r1.y * n1.y;
    float de2 = r2.x * n2.x + r2.y * n2.y;

    float loss = de0 + de1 + de2;

    float s0 = de0 * unpack_hi(z0);    // de * (1/area)
    float s1 = de1 * unpack_hi(z1);
    float s2 = de2 * unpack_hi(z2);

    float Ax = r0.x * s0 + r1.x * s1 + r2.x * s2;   // w*inva = uv
    float Ay = r0.y * s0 + r1.y * s1 + r2.y * s2;

    float q0 = unpack_lo(z0), q1 = unpack_lo(z1), q2 = unpack_lo(z2);
    float Px = q0 * n0.x + q1 * n1.x + q2 * n2.x;
    float Py = q0 * n0.y + q1 * n1.y + q2 * n2.y;

    float Dx = unpack_lo(w0) + unpack_lo(w1) + unpack_lo(w2);
    float Dy = unpack_hi(w0) + unpack_hi(w1) + unpack_hi(w2);

    float inv_rho = 1.0f / __ldcs(&rho[c]);
    float rc = __ldcs(&rhs_coef[c]);

    float ox = rc * (-Ax - inv_rho * Px) + Dx;
    float oy = rc * (-Ay - inv_rho * Py) + Dy;

    __stcs(&out[c], loss);                             // loss_continuity [C,1]
    float2* o2 = reinterpret_cast<float2*>(out + C);
    __stcs(&o2[c], make_float2(ox, oy));               // out [C,2]
}

extern "C" void kernel_launch(void* const* d_in, const int* in_sizes, int n_in,
                              void* d_out, int out_size) {
    // 0 uv_face [F,2] f32 | 1 p_face [F,1] f32 | 2 flux_D [F,2] f32
    // 3 unv [C,3,2] f32   | 4 rho [C,1] f32    | 5 rhs_coef [C,1] f32
    // 6 face_area [F,1] f32 | 7 cell_face [3,C] (int64 or downcast)
    const float2* uv_face   = (const float2*)d_in[0];
    const float*  p_face    = (const float*) d_in[1];
    const float2* flux_D    = (const float2*)d_in[2];
    const float2* unv       = (const float2*)d_in[3];
    const float*  rho       = (const float*) d_in[4];
    const float*  rhs_coef  = (const float*) d_in[5];
    const float*  face_area = (const float*) d_in[6];
    const void*   cell_face = d_in[7];

    int F = in_sizes[1];   // p_face element count
    int C = in_sizes[4];   // rho element count
    float* out = (float*)d_out;

    long long nwords = 3LL * C;

    const int TPB = 256;
    pack_faces_kernel<<<(F + TPB - 1) / TPB, TPB>>>(uv_face, p_face, flux_D, face_area,
                                                    (const unsigned int*)cell_face,
                                                    nwords, F);
    cell_integrate_kernel<<<(C + TPB - 1) / TPB, TPB>>>(cell_face, unv, rho, rhs_coef,
                                                        out, C, F);
}